// round 7
// baseline (speedup 1.0000x reference)
#include <cuda_runtime.h>
#include <math.h>

// ---------------------------------------------------------------------------
// Constants
// ---------------------------------------------------------------------------
#define BATCHN 128
#define MN     64
#define LAT    256
#define HID    512
#define GATES  1536
#define NPAIRS 2016
#define EPSG   1e-10f
#define NBLK   128   // persistent GRU grid size (<= 148 SMs -> wave-1 resident)

typedef unsigned long long ull;

// ---------------------------------------------------------------------------
// Static device scratch (no allocations anywhere)
// ---------------------------------------------------------------------------
__device__ float d_T1 [MN * LAT];                 // 64x256
__device__ float d_seq[BATCHN * MN * LAT];        // [b][t][256]
__device__ float d_gi [MN * BATCHN * GATES];      // [t][b][1536] (reused by both layers)
__device__ float d_h1 [BATCHN * MN * HID];        // layer0 outputs [b][t][512]
__device__ float d_h2 [BATCHN * MN * HID];        // layer1 outputs (masked) [b][t][512]
__device__ float d_hA [BATCHN * HID];             // h ping
__device__ float d_hB [BATCHN * HID];             // h pong
__device__ float d_Wb0[GATES * HID];              // Whh0 k-blocked [k4][1536][4]
__device__ float d_Wb1[GATES * HID];              // Whh1 k-blocked
__device__ float d_nWT[HID * HID];                // node_W transposed [k][d]
__device__ float d_WA [HID * HID];                // W1a @ node_W  (as [h][k])
__device__ float d_WB [HID * HID];                // W1b @ node_W
__device__ float d_Am [BATCHN * MN * HID];        // A[b,t,h]
__device__ float d_Bm [BATCHN * MN * HID];        // B[b,t,h]
__device__ int   d_pI [NPAIRS];
__device__ int   d_pJ [NPAIRS];
__device__ unsigned int d_bar;                    // grid-barrier epoch counter

// ---------------------------------------------------------------------------
// f32x2 helpers (B300: 3-reg FFMA is half rate; f32x2 restores full rate)
// ---------------------------------------------------------------------------
__device__ __forceinline__ void fma2(ull &c, ull a, ull b) {
    asm("fma.rn.f32x2 %0, %1, %2, %0;" : "+l"(c) : "l"(a), "l"(b));
}
__device__ __forceinline__ float2 unpack2(ull v) {
    float2 r;
    asm("mov.b64 {%0,%1}, %2;" : "=f"(r.x), "=f"(r.y) : "l"(v));
    return r;
}

// ---------------------------------------------------------------------------
// Barrier reset (launched before each persistent kernel; stream-ordered)
// ---------------------------------------------------------------------------
__global__ void k_reset() { d_bar = 0u; }

// ---------------------------------------------------------------------------
// Whh row-major [1536][512] -> k-blocked [k4][1536] float4
// (coalesced reads; scattered writes; one-time 3MB transform)
// ---------------------------------------------------------------------------
__global__ void k_blockW(const float4* __restrict__ W4, float4* __restrict__ Wb4) {
    int idx = blockIdx.x * 256 + threadIdx.x;     // over 1536*128 float4s
    int row = idx >> 7, k4 = idx & 127;
    Wb4[k4 * GATES + row] = W4[idx];
}

// ---------------------------------------------------------------------------
// Pair index table: np.triu_indices(64, k=1), row-major order
// ---------------------------------------------------------------------------
__global__ void k_init_pairs() {
    int i = threadIdx.x;
    if (i < MN - 1) {
        int start = i * (MN - 1) - i * (i - 1) / 2;
        for (int j = i + 1; j < MN; j++) {
            int p = start + (j - i - 1);
            d_pI[p] = i;
            d_pJ[p] = j;
        }
    }
}

// ---------------------------------------------------------------------------
// T1[t,o] = pe[t]·Wpre[o,:256] + emb[t]·Wpre[o,256:] + b_pre[o]
// ---------------------------------------------------------------------------
__global__ void k_T1(const float* __restrict__ pe, const float* __restrict__ emb,
                     const float* __restrict__ Wpre, const float* __restrict__ bpre) {
    int t = blockIdx.x, o = threadIdx.x;
    __shared__ float sp[LAT], se[LAT];
    sp[o] = pe[t * LAT + o];
    se[o] = emb[t * LAT + o];
    __syncthreads();
    const float* w = Wpre + o * 2 * LAT;
    float acc = bpre[o];
#pragma unroll 4
    for (int k = 0; k < LAT; k++)
        acc = fmaf(sp[k], w[k], fmaf(se[k], w[LAT + k], acc));
    d_T1[t * LAT + o] = acc;
}

// ---------------------------------------------------------------------------
// seq[b,t,o] = (z[b]·Wpre[o,:256] + T1[t,o]) * (t < n_nodes[b])
// ---------------------------------------------------------------------------
__global__ void k_seq(const float* __restrict__ z, const int* __restrict__ n_nodes,
                      const float* __restrict__ Wpre) {
    int b = blockIdx.x, o = threadIdx.x;
    __shared__ float sz[LAT];
    sz[o] = z[b * LAT + o];
    __syncthreads();
    const float* w = Wpre + o * 2 * LAT;
    float acc = 0.f;
#pragma unroll 4
    for (int k = 0; k < LAT; k++)
        acc = fmaf(sz[k], w[k], acc);
    int nb = n_nodes[b];
    for (int t = 0; t < MN; t++)
        d_seq[(b * MN + t) * LAT + o] = (t < nb) ? acc + d_T1[t * LAT + o] : 0.f;
}

// ---------------------------------------------------------------------------
// Generic NT GEMM: C[M][N] = A[M][K] * B[N][K]^T (+ bias[N])
//   remap=1: logical row m reads A at ((m%128)*64 + m/128)*ldA   (t-major gi)
//   BM=BN=64, BK=16, 256 threads, per-thread 4x4 via f32x2 (K-parity packed)
//   Double-buffered smem: prefetch next tile to regs while computing, ONE
//   __syncthreads per tile.
// ---------------------------------------------------------------------------
__global__ __launch_bounds__(256, 2)
void k_gemm(const float* __restrict__ A, int ldA, int remap,
            const float* __restrict__ B, int ldB,
            const float* __restrict__ bias,
            float* __restrict__ C, int N, int K) {
    __shared__ float As[2][64 * 18];
    __shared__ float Bs[2][64 * 18];
    int tid = threadIdx.x;
    int ty = tid >> 4, tx = tid & 15;
    int m0 = blockIdx.x * 64, n0 = blockIdx.y * 64;
    int lrow = tid >> 2, kq = tid & 3;
    int sb = lrow * 18 + kq * 4;

    long aoff;
    {
        int arow = m0 + lrow;
        if (remap) {
            int bb = arow & 127, tt = arow >> 7;
            aoff = (long)(bb * MN + tt) * ldA;
        } else {
            aoff = (long)arow * ldA;
        }
    }
    long boff = (long)(n0 + lrow) * ldB;

    ull c2[4][4];
#pragma unroll
    for (int i = 0; i < 4; i++)
#pragma unroll
        for (int j = 0; j < 4; j++) c2[i][j] = 0ull;

    // preload tile 0
    {
        float4 av = *(const float4*)(A + aoff + kq * 4);
        float4 bv = *(const float4*)(B + boff + kq * 4);
        *(float2*)&As[0][sb]     = make_float2(av.x, av.y);
        *(float2*)&As[0][sb + 2] = make_float2(av.z, av.w);
        *(float2*)&Bs[0][sb]     = make_float2(bv.x, bv.y);
        *(float2*)&Bs[0][sb + 2] = make_float2(bv.z, bv.w);
    }
    __syncthreads();

    int buf = 0;
    for (int k0 = 0; k0 < K; k0 += 16) {
        bool more = (k0 + 16) < K;
        float4 av, bv;
        if (more) {
            av = *(const float4*)(A + aoff + k0 + 16 + kq * 4);
            bv = *(const float4*)(B + boff + k0 + 16 + kq * 4);
        }
#pragma unroll
        for (int kk = 0; kk < 16; kk += 2) {
            ull a2[4], b2[4];
#pragma unroll
            for (int i = 0; i < 4; i++) a2[i] = *(const ull*)&As[buf][(ty + 16 * i) * 18 + kk];
#pragma unroll
            for (int j = 0; j < 4; j++) b2[j] = *(const ull*)&Bs[buf][(tx + 16 * j) * 18 + kk];
#pragma unroll
            for (int i = 0; i < 4; i++)
#pragma unroll
                for (int j = 0; j < 4; j++) fma2(c2[i][j], a2[i], b2[j]);
        }
        if (more) {
            int nb = buf ^ 1;
            *(float2*)&As[nb][sb]     = make_float2(av.x, av.y);
            *(float2*)&As[nb][sb + 2] = make_float2(av.z, av.w);
            *(float2*)&Bs[nb][sb]     = make_float2(bv.x, bv.y);
            *(float2*)&Bs[nb][sb + 2] = make_float2(bv.z, bv.w);
        }
        __syncthreads();
        buf ^= 1;
    }

#pragma unroll
    for (int i = 0; i < 4; i++) {
        int m = m0 + ty + 16 * i;
#pragma unroll
        for (int j = 0; j < 4; j++) {
            int n = n0 + tx + 16 * j;
            float2 v = unpack2(c2[i][j]);
            float val = v.x + v.y;
            if (bias) val += bias[n];
            C[(long)m * N + n] = val;
        }
    }
}

// ---------------------------------------------------------------------------
// Persistent GRU layer: all 64 steps in one launch, 128 resident CTAs,
// device-side epoch barrier between steps. Block = (batch-tile bx of 8) x
// (col-tile by of 64 cols x 3 gates = 192 rows).
// Whh comes in k-blocked layout Wblk[k4][1536] (float4 = 4 consecutive k per
// row) so each warp-load covers 32 consecutive rows -> coalesced.
// ---------------------------------------------------------------------------
__global__ __launch_bounds__(192)
void k_gru_persist(const float* __restrict__ gi,
                   const ulonglong2* __restrict__ Wblk,   // [k4][1536] (16B each)
                   const float* __restrict__ bhh,
                   float* __restrict__ hA, float* __restrict__ hB,
                   float* __restrict__ yout, const int* __restrict__ n_nodes,
                   int maskout) {
    __shared__ float h_sh[8 * 512];
    __shared__ float gh_sh[8 * 192];
    int tid = threadIdx.x;
    int bx = blockIdx.x & 15;      // batch tile (16)
    int by = blockIdx.x >> 4;      // col tile (8)
    int b0 = bx * 8;

    int g = tid / 64, j = tid % 64;
    int row = g * 512 + by * 64 + j;
    const float bh = bhh[row];
    const ulonglong2* wp = Wblk + row;   // advance by GATES per k4

    // h(-1) = 0
    {
        float4 z4 = make_float4(0.f, 0.f, 0.f, 0.f);
        for (int idx = tid; idx < 1024; idx += 192) ((float4*)h_sh)[idx] = z4;
    }
    __syncthreads();

    for (int step = 0; step < MN; step++) {
        // --- gh = Whh_row . h(step-1) for 8 batches -------------------------
        ull acc[8];
#pragma unroll
        for (int b = 0; b < 8; b++) acc[b] = 0ull;
#pragma unroll 8
        for (int k4 = 0; k4 < 128; k4++) {
            ulonglong2 wv = wp[(long)k4 * GATES];   // coalesced across warp
#pragma unroll
            for (int b = 0; b < 8; b++) {
                ulonglong2 hv = *(const ulonglong2*)(h_sh + b * 512 + k4 * 4);
                fma2(acc[b], wv.x, hv.x);
                fma2(acc[b], wv.y, hv.y);
            }
        }
#pragma unroll
        for (int b = 0; b < 8; b++) {
            float2 v = unpack2(acc[b]);
            gh_sh[b * 192 + tid] = v.x + v.y + bh;
        }
        __syncthreads();

        // --- gate math + state update (h_sh still holds old h) --------------
        float* hw = (step & 1) ? hB : hA;   // h(step) lives here
        for (int idx = tid; idx < 512; idx += 192) {
            int b = idx >> 6, jj = idx & 63;
            int gb = b0 + b;
            int col = by * 64 + jj;
            long gbase = ((long)step * 128 + gb) * GATES;
            float ir  = gi[gbase + col];
            float iz  = gi[gbase + 512 + col];
            float inn = gi[gbase + 1024 + col];
            float hr = gh_sh[b * 192 + jj];
            float hz = gh_sh[b * 192 + 64 + jj];
            float hn = gh_sh[b * 192 + 128 + jj];
            float r  = 1.f / (1.f + expf(-(ir + hr)));
            float zg = 1.f / (1.f + expf(-(iz + hz)));
            float nn = tanhf(fmaf(r, hn, inn));
            float hold = h_sh[b * 512 + col];
            float hnew = (1.f - zg) * nn + zg * hold;
            hw[gb * 512 + col] = hnew;
            float yv = hnew;
            if (maskout && step >= n_nodes[gb]) yv = 0.f;
            yout[((long)gb * MN + step) * HID + col] = yv;
        }

        if (step == MN - 1) break;

        // --- grid barrier ---------------------------------------------------
        __syncthreads();            // all warps done writing h(step)
        if (tid == 0) {
            __threadfence();        // make h(step) visible before arriving
            atomicAdd(&d_bar, 1u);
            unsigned int target = (unsigned int)(step + 1) * NBLK;
            while (*((volatile unsigned int*)&d_bar) < target) { }
        }
        __syncthreads();
        __threadfence();

        // --- reload full h(step) for my 8 batches (bypass L1: cross-SM data)
        const float4* hr4 = (const float4*)hw;
        for (int idx = tid; idx < 1024; idx += 192)
            ((float4*)h_sh)[idx] = __ldcv(hr4 + b0 * 128 + idx);
        __syncthreads();
    }
}

// ---------------------------------------------------------------------------
// 512x512 transpose: dst[k][d] = src[d][k]
// ---------------------------------------------------------------------------
__global__ void k_transpose(const float* __restrict__ src, float* __restrict__ dst) {
    __shared__ float tile[32][33];
    int x = blockIdx.x * 32 + threadIdx.x;
    int y0 = blockIdx.y * 32;
    for (int r = threadIdx.y; r < 32; r += 8)
        tile[r][threadIdx.x] = src[(y0 + r) * HID + x];
    __syncthreads();
    int xo = blockIdx.y * 32 + threadIdx.x;
    int yo0 = blockIdx.x * 32;
    for (int r = threadIdx.y; r < 32; r += 8)
        dst[(yo0 + r) * HID + xo] = tile[threadIdx.x][r];
}

// ---------------------------------------------------------------------------
// Pair head: ld = sum_h relu(A[b,i,h]+B[b,j,h]+b1[h]) * (W2[0,h]-W2[1,h]) + b2d
// vals = 1 if ld + g0 - g1 >= 0. Writes only the 1s (out pre-zeroed).
// b1 and w2-diff staged in smem; float4 loads of A/B rows.
// ---------------------------------------------------------------------------
__global__ __launch_bounds__(256)
void k_pairs(const float* __restrict__ gum, const int* __restrict__ n_nodes,
             const float* __restrict__ b1, const float* __restrict__ W2,
             const float* __restrict__ b2, float* __restrict__ out) {
    __shared__ float b1s[HID], w2s[HID];
    int b = blockIdx.y;
    int tid = threadIdx.x;
    for (int k = tid; k < HID; k += 256) {
        b1s[k] = b1[k];
        w2s[k] = W2[k] - W2[HID + k];
    }
    __syncthreads();
    int w = tid >> 5, lane = tid & 31;
    int nb = n_nodes[b];
    float b2d = b2[0] - b2[1];
#pragma unroll
    for (int q = 0; q < 2; q++) {
        int p = blockIdx.x * 16 + w * 2 + q;
        int i = d_pI[p], j = d_pJ[p];
        const float4* Ar = (const float4*)(d_Am + ((long)b * MN + i) * HID);
        const float4* Br = (const float4*)(d_Bm + ((long)b * MN + j) * HID);
        float acc = 0.f;
#pragma unroll
        for (int it = 0; it < 4; it++) {
            int k4 = it * 32 + lane;
            float4 a4 = Ar[k4];
            float4 b4 = Br[k4];
            int k = k4 * 4;
            float h0 = fmaxf(a4.x + b4.x + b1s[k],     0.f);
            float h1 = fmaxf(a4.y + b4.y + b1s[k + 1], 0.f);
            float h2 = fmaxf(a4.z + b4.z + b1s[k + 2], 0.f);
            float h3 = fmaxf(a4.w + b4.w + b1s[k + 3], 0.f);
            acc = fmaf(h0, w2s[k], acc);
            acc = fmaf(h1, w2s[k + 1], acc);
            acc = fmaf(h2, w2s[k + 2], acc);
            acc = fmaf(h3, w2s[k + 3], acc);
        }
#pragma unroll
        for (int off = 16; off; off >>= 1)
            acc += __shfl_xor_sync(0xffffffffu, acc, off);
        if (lane == 0 && j < nb) {
            const float* gu = gum + ((long)b * NPAIRS + p) * 2;
            float g0 = -logf(-logf(gu[0] + EPSG) + EPSG);
            float g1 = -logf(-logf(gu[1] + EPSG) + EPSG);
            float s = acc + b2d + g0 - g1;
            if (s >= 0.f) {
                out[(long)b * (MN * MN) + i * MN + j] = 1.f;
                out[(long)b * (MN * MN) + j * MN + i] = 1.f;
            }
        }
    }
}

// ---------------------------------------------------------------------------
// Host launch
// ---------------------------------------------------------------------------
extern "C" void kernel_launch(void* const* d_in, const int* in_sizes, int n_in,
                              void* d_out, int out_size) {
    // n_edges is an unused scalar; hedge on whether it appears as an input.
    int s = (n_in >= 21) ? 1 : 0;
    const float* z    = (const float*)d_in[0];
    const int*   nn   = (const int*)  d_in[1];
    const float* gum  = (const float*)d_in[2 + s];
    const float* emb  = (const float*)d_in[3 + s];
    const float* pe   = (const float*)d_in[4 + s];
    const float* Wpre = (const float*)d_in[5 + s];
    const float* bpre = (const float*)d_in[6 + s];
    const float* Wih0 = (const float*)d_in[7 + s];
    const float* Whh0 = (const float*)d_in[8 + s];
    const float* bih0 = (const float*)d_in[9 + s];
    const float* bhh0 = (const float*)d_in[10 + s];
    const float* Wih1 = (const float*)d_in[11 + s];
    const float* Whh1 = (const float*)d_in[12 + s];
    const float* bih1 = (const float*)d_in[13 + s];
    const float* bhh1 = (const float*)d_in[14 + s];
    const float* nW   = (const float*)d_in[15 + s];
    const float* aW1  = (const float*)d_in[16 + s];
    const float* ab1  = (const float*)d_in[17 + s];
    const float* aW2  = (const float*)d_in[18 + s];
    const float* ab2  = (const float*)d_in[19 + s];
    float* out = (float*)d_out;
    (void)in_sizes;

    float *seqp, *gip, *h1p, *h2p, *hAp, *hBp, *nWTp, *WAp, *WBp, *Amp, *Bmp;
    float *Wb0p, *Wb1p;
    cudaGetSymbolAddress((void**)&seqp, d_seq);
    cudaGetSymbolAddress((void**)&gip,  d_gi);
    cudaGetSymbolAddress((void**)&h1p,  d_h1);
    cudaGetSymbolAddress((void**)&h2p,  d_h2);
    cudaGetSymbolAddress((void**)&hAp,  d_hA);
    cudaGetSymbolAddress((void**)&hBp,  d_hB);
    cudaGetSymbolAddress((void**)&nWTp, d_nWT);
    cudaGetSymbolAddress((void**)&WAp,  d_WA);
    cudaGetSymbolAddress((void**)&WBp,  d_WB);
    cudaGetSymbolAddress((void**)&Amp,  d_Am);
    cudaGetSymbolAddress((void**)&Bmp,  d_Bm);
    cudaGetSymbolAddress((void**)&Wb0p, d_Wb0);
    cudaGetSymbolAddress((void**)&Wb1p, d_Wb1);

    k_init_pairs<<<1, 64>>>();
    k_T1<<<64, 256>>>(pe, emb, Wpre, bpre);
    k_seq<<<128, 256>>>(z, nn, Wpre);
    k_blockW<<<768, 256>>>((const float4*)Whh0, (float4*)Wb0p);
    k_blockW<<<768, 256>>>((const float4*)Whh1, (float4*)Wb1p);

    // Layer 0: gi = seq @ Wih0^T + bih0   (M=8192, N=1536, K=256)
    k_gemm<<<dim3(128, 24), 256>>>(seqp, LAT, 1, Wih0, LAT, bih0, gip, GATES, LAT);
    k_reset<<<1, 1>>>();
    k_gru_persist<<<NBLK, 192>>>(gip, (const ulonglong2*)Wb0p, bhh0, hAp, hBp, h1p, nn, 0);

    // Layer 1: gi = h1 @ Wih1^T + bih1    (M=8192, N=1536, K=512)
    k_gemm<<<dim3(128, 24), 256>>>(h1p, HID, 1, Wih1, HID, bih1, gip, GATES, HID);
    k_reset<<<1, 1>>>();
    k_gru_persist<<<NBLK, 192>>>(gip, (const ulonglong2*)Wb1p, bhh1, hAp, hBp, h2p, nn, 1);

    // Fold node_W into adjacency weights: WA = W1a @ node_W, WB = W1b @ node_W
    k_transpose<<<dim3(16, 16), dim3(32, 8)>>>(nW, nWTp);
    k_gemm<<<dim3(8, 8), 256>>>(aW1,       2 * HID, 0, nWTp, HID, nullptr, WAp, HID, HID);
    k_gemm<<<dim3(8, 8), 256>>>(aW1 + HID, 2 * HID, 0, nWTp, HID, nullptr, WBp, HID, HID);

    // A = rnn_out @ WA^T, B = rnn_out @ WB^T  (M=8192, N=512, K=512)
    k_gemm<<<dim3(128, 8), 256>>>(h2p, HID, 0, WAp, HID, nullptr, Amp, HID, HID);
    k_gemm<<<dim3(128, 8), 256>>>(h2p, HID, 0, WBp, HID, nullptr, Bmp, HID, HID);

    cudaMemsetAsync(out, 0, (size_t)out_size * sizeof(float), 0);
    k_pairs<<<dim3(126, 128), 256>>>(gum, nn, ab1, aW2, ab2, out);
}

// round 8
// speedup vs baseline: 1.4402x; 1.4402x over previous
#include <cuda_runtime.h>
#include <math.h>

// ---------------------------------------------------------------------------
// Constants
// ---------------------------------------------------------------------------
#define BATCHN 128
#define MN     64
#define LAT    256
#define HID    512
#define GATES  1536
#define NPAIRS 2016
#define EPSG   1e-10f
#define NBLK   128   // persistent GRU grid size (<= 148 SMs -> wave-1 resident)

typedef unsigned long long ull;

// ---------------------------------------------------------------------------
// Static device scratch (no allocations anywhere)
// ---------------------------------------------------------------------------
__device__ float d_T1 [MN * LAT];                 // 64x256
__device__ float d_seq[BATCHN * MN * LAT];        // [b][t][256]
__device__ float d_gi [MN * BATCHN * GATES];      // [t][b][1536] (reused by both layers)
__device__ float d_h1 [BATCHN * MN * HID];        // layer0 outputs [b][t][512]
__device__ float d_h2 [BATCHN * MN * HID];        // layer1 outputs (masked) [b][t][512]
__device__ float d_hA [BATCHN * HID];             // h ping
__device__ float d_hB [BATCHN * HID];             // h pong
__device__ float d_Wb0[GATES * HID];              // Whh0 k-blocked [k4][1536][4]
__device__ float d_Wb1[GATES * HID];              // Whh1 k-blocked
__device__ float d_nWT[HID * HID];                // node_W transposed [k][d]
__device__ float d_WA [HID * HID];                // W1a @ node_W  (as [h][k])
__device__ float d_WB [HID * HID];                // W1b @ node_W
__device__ float d_Am [BATCHN * MN * HID];        // A[b,t,h]
__device__ float d_Bm [BATCHN * MN * HID];        // B[b,t,h]
__device__ int   d_pI [NPAIRS];
__device__ int   d_pJ [NPAIRS];
__device__ unsigned int d_bar;                    // grid-barrier epoch counter

// ---------------------------------------------------------------------------
// f32x2 helpers (B300: 3-reg FFMA is half rate; f32x2 restores full rate)
// ---------------------------------------------------------------------------
__device__ __forceinline__ void fma2(ull &c, ull a, ull b) {
    asm("fma.rn.f32x2 %0, %1, %2, %0;" : "+l"(c) : "l"(a), "l"(b));
}
__device__ __forceinline__ float2 unpack2(ull v) {
    float2 r;
    asm("mov.b64 {%0,%1}, %2;" : "=f"(r.x), "=f"(r.y) : "l"(v));
    return r;
}

// ---------------------------------------------------------------------------
// Barrier reset (launched before each persistent kernel; stream-ordered)
// ---------------------------------------------------------------------------
__global__ void k_reset() { d_bar = 0u; }

// ---------------------------------------------------------------------------
// Whh row-major [1536][512] -> k-blocked [k4][1536] float4
// (coalesced reads; scattered writes; one-time 3MB transform)
// ---------------------------------------------------------------------------
__global__ void k_blockW(const float4* __restrict__ W4, float4* __restrict__ Wb4) {
    int idx = blockIdx.x * 256 + threadIdx.x;     // over 1536*128 float4s
    int row = idx >> 7, k4 = idx & 127;
    Wb4[k4 * GATES + row] = W4[idx];
}

// ---------------------------------------------------------------------------
// Pair index table: np.triu_indices(64, k=1), row-major order
// ---------------------------------------------------------------------------
__global__ void k_init_pairs() {
    int i = threadIdx.x;
    if (i < MN - 1) {
        int start = i * (MN - 1) - i * (i - 1) / 2;
        for (int j = i + 1; j < MN; j++) {
            int p = start + (j - i - 1);
            d_pI[p] = i;
            d_pJ[p] = j;
        }
    }
}

// ---------------------------------------------------------------------------
// T1[t,o] = pe[t]·Wpre[o,:256] + emb[t]·Wpre[o,256:] + b_pre[o]
// ---------------------------------------------------------------------------
__global__ void k_T1(const float* __restrict__ pe, const float* __restrict__ emb,
                     const float* __restrict__ Wpre, const float* __restrict__ bpre) {
    int t = blockIdx.x, o = threadIdx.x;
    __shared__ float sp[LAT], se[LAT];
    sp[o] = pe[t * LAT + o];
    se[o] = emb[t * LAT + o];
    __syncthreads();
    const float* w = Wpre + o * 2 * LAT;
    float acc = bpre[o];
#pragma unroll 4
    for (int k = 0; k < LAT; k++)
        acc = fmaf(sp[k], w[k], fmaf(se[k], w[LAT + k], acc));
    d_T1[t * LAT + o] = acc;
}

// ---------------------------------------------------------------------------
// seq[b,t,o] = (z[b]·Wpre[o,:256] + T1[t,o]) * (t < n_nodes[b])
// ---------------------------------------------------------------------------
__global__ void k_seq(const float* __restrict__ z, const int* __restrict__ n_nodes,
                      const float* __restrict__ Wpre) {
    int b = blockIdx.x, o = threadIdx.x;
    __shared__ float sz[LAT];
    sz[o] = z[b * LAT + o];
    __syncthreads();
    const float* w = Wpre + o * 2 * LAT;
    float acc = 0.f;
#pragma unroll 4
    for (int k = 0; k < LAT; k++)
        acc = fmaf(sz[k], w[k], acc);
    int nb = n_nodes[b];
    for (int t = 0; t < MN; t++)
        d_seq[(b * MN + t) * LAT + o] = (t < nb) ? acc + d_T1[t * LAT + o] : 0.f;
}

// ---------------------------------------------------------------------------
// Generic NT GEMM: C[M][N] = A[M][K] * B[N][K]^T (+ bias[N])
//   remap=1: logical row m reads A at ((m%128)*64 + m/128)*ldA   (t-major gi)
//   BM=BN=64, BK=16, 256 threads, per-thread 4x4 via f32x2 (K-parity packed)
//   (round-6 single-buffer version: 92 regs, no spills)
// ---------------------------------------------------------------------------
__global__ __launch_bounds__(256, 2)
void k_gemm(const float* __restrict__ A, int ldA, int remap,
            const float* __restrict__ B, int ldB,
            const float* __restrict__ bias,
            float* __restrict__ C, int N, int K) {
    __shared__ float As[64 * 18];
    __shared__ float Bs[64 * 18];
    int tid = threadIdx.x;
    int ty = tid >> 4, tx = tid & 15;
    int m0 = blockIdx.x * 64, n0 = blockIdx.y * 64;
    int lrow = tid >> 2, kq = tid & 3;

    long aoff;
    {
        int arow = m0 + lrow;
        if (remap) {
            int bb = arow & 127, tt = arow >> 7;
            aoff = (long)(bb * MN + tt) * ldA;
        } else {
            aoff = (long)arow * ldA;
        }
    }
    long boff = (long)(n0 + lrow) * ldB;

    ull c2[4][4];
#pragma unroll
    for (int i = 0; i < 4; i++)
#pragma unroll
        for (int j = 0; j < 4; j++) c2[i][j] = 0ull;

    for (int k0 = 0; k0 < K; k0 += 16) {
        float4 av = *(const float4*)(A + aoff + k0 + kq * 4);
        float4 bv = *(const float4*)(B + boff + k0 + kq * 4);
        int sb = lrow * 18 + kq * 4;
        *(float2*)&As[sb]     = make_float2(av.x, av.y);
        *(float2*)&As[sb + 2] = make_float2(av.z, av.w);
        *(float2*)&Bs[sb]     = make_float2(bv.x, bv.y);
        *(float2*)&Bs[sb + 2] = make_float2(bv.z, bv.w);
        __syncthreads();
#pragma unroll
        for (int kk = 0; kk < 16; kk += 2) {
            ull a2[4], b2[4];
#pragma unroll
            for (int i = 0; i < 4; i++) a2[i] = *(const ull*)&As[(ty + 16 * i) * 18 + kk];
#pragma unroll
            for (int j = 0; j < 4; j++) b2[j] = *(const ull*)&Bs[(tx + 16 * j) * 18 + kk];
#pragma unroll
            for (int i = 0; i < 4; i++)
#pragma unroll
                for (int j = 0; j < 4; j++) fma2(c2[i][j], a2[i], b2[j]);
        }
        __syncthreads();
    }

#pragma unroll
    for (int i = 0; i < 4; i++) {
        int m = m0 + ty + 16 * i;
#pragma unroll
        for (int j = 0; j < 4; j++) {
            int n = n0 + tx + 16 * j;
            float2 v = unpack2(c2[i][j]);
            float val = v.x + v.y;
            if (bias) val += bias[n];
            C[(long)m * N + n] = val;
        }
    }
}

// ---------------------------------------------------------------------------
// Persistent GRU layer: all 64 steps in one launch, 128 resident CTAs,
// device-side epoch barrier between steps. Block = (batch-tile bx of 8) x
// (col-tile by of 64 cols x 3 gates = 192 rows).
// Whh comes in k-blocked layout Wblk[k4][1536] (float4 = 4 consecutive k per
// row) so each warp-load covers 32 consecutive rows -> coalesced (4 L1tex
// wavefronts/load instead of 32 with row-major).
// ---------------------------------------------------------------------------
__global__ __launch_bounds__(192)
void k_gru_persist(const float* __restrict__ gi,
                   const ulonglong2* __restrict__ Wblk,   // [k4][1536] (16B each)
                   const float* __restrict__ bhh,
                   float* __restrict__ hA, float* __restrict__ hB,
                   float* __restrict__ yout, const int* __restrict__ n_nodes,
                   int maskout) {
    __shared__ float h_sh[8 * 512];
    __shared__ float gh_sh[8 * 192];
    int tid = threadIdx.x;
    int bx = blockIdx.x & 15;      // batch tile (16)
    int by = blockIdx.x >> 4;      // col tile (8)
    int b0 = bx * 8;

    int g = tid / 64, j = tid % 64;
    int row = g * 512 + by * 64 + j;
    const float bh = bhh[row];
    const ulonglong2* wp = Wblk + row;   // advance by GATES per k4

    // h(-1) = 0
    {
        float4 z4 = make_float4(0.f, 0.f, 0.f, 0.f);
        for (int idx = tid; idx < 1024; idx += 192) ((float4*)h_sh)[idx] = z4;
    }
    __syncthreads();

    for (int step = 0; step < MN; step++) {
        // --- gh = Whh_row . h(step-1) for 8 batches -------------------------
        ull acc[8];
#pragma unroll
        for (int b = 0; b < 8; b++) acc[b] = 0ull;
#pragma unroll 8
        for (int k4 = 0; k4 < 128; k4++) {
            ulonglong2 wv = wp[(long)k4 * GATES];   // coalesced across warp
#pragma unroll
            for (int b = 0; b < 8; b++) {
                ulonglong2 hv = *(const ulonglong2*)(h_sh + b * 512 + k4 * 4);
                fma2(acc[b], wv.x, hv.x);
                fma2(acc[b], wv.y, hv.y);
            }
        }
#pragma unroll
        for (int b = 0; b < 8; b++) {
            float2 v = unpack2(acc[b]);
            gh_sh[b * 192 + tid] = v.x + v.y + bh;
        }
        __syncthreads();

        // --- gate math + state update (h_sh still holds old h) --------------
        float* hw = (step & 1) ? hB : hA;   // h(step) lives here
        for (int idx = tid; idx < 512; idx += 192) {
            int b = idx >> 6, jj = idx & 63;
            int gb = b0 + b;
            int col = by * 64 + jj;
            long gbase = ((long)step * 128 + gb) * GATES;
            float ir  = gi[gbase + col];
            float iz  = gi[gbase + 512 + col];
            float inn = gi[gbase + 1024 + col];
            float hr = gh_sh[b * 192 + jj];
            float hz = gh_sh[b * 192 + 64 + jj];
            float hn = gh_sh[b * 192 + 128 + jj];
            float r  = 1.f / (1.f + expf(-(ir + hr)));
            float zg = 1.f / (1.f + expf(-(iz + hz)));
            float nn = tanhf(fmaf(r, hn, inn));
            float hold = h_sh[b * 512 + col];
            float hnew = (1.f - zg) * nn + zg * hold;
            hw[gb * 512 + col] = hnew;
            float yv = hnew;
            if (maskout && step >= n_nodes[gb]) yv = 0.f;
            yout[((long)gb * MN + step) * HID + col] = yv;
        }

        if (step == MN - 1) break;

        // --- grid barrier ---------------------------------------------------
        __syncthreads();            // all warps done writing h(step)
        if (tid == 0) {
            __threadfence();        // make h(step) visible before arriving
            atomicAdd(&d_bar, 1u);
            unsigned int target = (unsigned int)(step + 1) * NBLK;
            while (*((volatile unsigned int*)&d_bar) < target) { }
        }
        __syncthreads();
        __threadfence();

        // --- reload full h(step) for my 8 batches (bypass L1: cross-SM data)
        const float4* hr4 = (const float4*)hw;
        for (int idx = tid; idx < 1024; idx += 192)
            ((float4*)h_sh)[idx] = __ldcv(hr4 + b0 * 128 + idx);
        __syncthreads();
    }
}

// ---------------------------------------------------------------------------
// 512x512 transpose: dst[k][d] = src[d][k]
// ---------------------------------------------------------------------------
__global__ void k_transpose(const float* __restrict__ src, float* __restrict__ dst) {
    __shared__ float tile[32][33];
    int x = blockIdx.x * 32 + threadIdx.x;
    int y0 = blockIdx.y * 32;
    for (int r = threadIdx.y; r < 32; r += 8)
        tile[r][threadIdx.x] = src[(y0 + r) * HID + x];
    __syncthreads();
    int xo = blockIdx.y * 32 + threadIdx.x;
    int yo0 = blockIdx.x * 32;
    for (int r = threadIdx.y; r < 32; r += 8)
        dst[(yo0 + r) * HID + xo] = tile[threadIdx.x][r];
}

// ---------------------------------------------------------------------------
// Pair head: ld = sum_h relu(A[b,i,h]+B[b,j,h]+b1[h]) * (W2[0,h]-W2[1,h]) + b2d
// vals = 1 if ld + g0 - g1 >= 0. Writes only the 1s (out pre-zeroed).
// b1 and w2-diff staged in smem; float4 loads of A/B rows.
// ---------------------------------------------------------------------------
__global__ __launch_bounds__(256)
void k_pairs(const float* __restrict__ gum, const int* __restrict__ n_nodes,
             const float* __restrict__ b1, const float* __restrict__ W2,
             const float* __restrict__ b2, float* __restrict__ out) {
    __shared__ float b1s[HID], w2s[HID];
    int b = blockIdx.y;
    int tid = threadIdx.x;
    for (int k = tid; k < HID; k += 256) {
        b1s[k] = b1[k];
        w2s[k] = W2[k] - W2[HID + k];
    }
    __syncthreads();
    int w = tid >> 5, lane = tid & 31;
    int nb = n_nodes[b];
    float b2d = b2[0] - b2[1];
#pragma unroll
    for (int q = 0; q < 2; q++) {
        int p = blockIdx.x * 16 + w * 2 + q;
        int i = d_pI[p], j = d_pJ[p];
        const float4* Ar = (const float4*)(d_Am + ((long)b * MN + i) * HID);
        const float4* Br = (const float4*)(d_Bm + ((long)b * MN + j) * HID);
        float acc = 0.f;
#pragma unroll
        for (int it = 0; it < 4; it++) {
            int k4 = it * 32 + lane;
            float4 a4 = Ar[k4];
            float4 b4 = Br[k4];
            int k = k4 * 4;
            float h0 = fmaxf(a4.x + b4.x + b1s[k],     0.f);
            float h1 = fmaxf(a4.y + b4.y + b1s[k + 1], 0.f);
            float h2 = fmaxf(a4.z + b4.z + b1s[k + 2], 0.f);
            float h3 = fmaxf(a4.w + b4.w + b1s[k + 3], 0.f);
            acc = fmaf(h0, w2s[k], acc);
            acc = fmaf(h1, w2s[k + 1], acc);
            acc = fmaf(h2, w2s[k + 2], acc);
            acc = fmaf(h3, w2s[k + 3], acc);
        }
#pragma unroll
        for (int off = 16; off; off >>= 1)
            acc += __shfl_xor_sync(0xffffffffu, acc, off);
        if (lane == 0 && j < nb) {
            const float* gu = gum + ((long)b * NPAIRS + p) * 2;
            float g0 = -logf(-logf(gu[0] + EPSG) + EPSG);
            float g1 = -logf(-logf(gu[1] + EPSG) + EPSG);
            float s = acc + b2d + g0 - g1;
            if (s >= 0.f) {
                out[(long)b * (MN * MN) + i * MN + j] = 1.f;
                out[(long)b * (MN * MN) + j * MN + i] = 1.f;
            }
        }
    }
}

// ---------------------------------------------------------------------------
// Host launch
// ---------------------------------------------------------------------------
extern "C" void kernel_launch(void* const* d_in, const int* in_sizes, int n_in,
                              void* d_out, int out_size) {
    // n_edges is an unused scalar; hedge on whether it appears as an input.
    int s = (n_in >= 21) ? 1 : 0;
    const float* z    = (const float*)d_in[0];
    const int*   nn   = (const int*)  d_in[1];
    const float* gum  = (const float*)d_in[2 + s];
    const float* emb  = (const float*)d_in[3 + s];
    const float* pe   = (const float*)d_in[4 + s];
    const float* Wpre = (const float*)d_in[5 + s];
    const float* bpre = (const float*)d_in[6 + s];
    const float* Wih0 = (const float*)d_in[7 + s];
    const float* Whh0 = (const float*)d_in[8 + s];
    const float* bih0 = (const float*)d_in[9 + s];
    const float* bhh0 = (const float*)d_in[10 + s];
    const float* Wih1 = (const float*)d_in[11 + s];
    const float* Whh1 = (const float*)d_in[12 + s];
    const float* bih1 = (const float*)d_in[13 + s];
    const float* bhh1 = (const float*)d_in[14 + s];
    const float* nW   = (const float*)d_in[15 + s];
    const float* aW1  = (const float*)d_in[16 + s];
    const float* ab1  = (const float*)d_in[17 + s];
    const float* aW2  = (const float*)d_in[18 + s];
    const float* ab2  = (const float*)d_in[19 + s];
    float* out = (float*)d_out;
    (void)in_sizes;

    float *seqp, *gip, *h1p, *h2p, *hAp, *hBp, *nWTp, *WAp, *WBp, *Amp, *Bmp;
    float *Wb0p, *Wb1p;
    cudaGetSymbolAddress((void**)&seqp, d_seq);
    cudaGetSymbolAddress((void**)&gip,  d_gi);
    cudaGetSymbolAddress((void**)&h1p,  d_h1);
    cudaGetSymbolAddress((void**)&h2p,  d_h2);
    cudaGetSymbolAddress((void**)&hAp,  d_hA);
    cudaGetSymbolAddress((void**)&hBp,  d_hB);
    cudaGetSymbolAddress((void**)&nWTp, d_nWT);
    cudaGetSymbolAddress((void**)&WAp,  d_WA);
    cudaGetSymbolAddress((void**)&WBp,  d_WB);
    cudaGetSymbolAddress((void**)&Amp,  d_Am);
    cudaGetSymbolAddress((void**)&Bmp,  d_Bm);
    cudaGetSymbolAddress((void**)&Wb0p, d_Wb0);
    cudaGetSymbolAddress((void**)&Wb1p, d_Wb1);

    k_init_pairs<<<1, 64>>>();
    k_T1<<<64, 256>>>(pe, emb, Wpre, bpre);
    k_seq<<<128, 256>>>(z, nn, Wpre);
    k_blockW<<<768, 256>>>((const float4*)Whh0, (float4*)Wb0p);
    k_blockW<<<768, 256>>>((const float4*)Whh1, (float4*)Wb1p);

    // Layer 0: gi = seq @ Wih0^T + bih0   (M=8192, N=1536, K=256)
    k_gemm<<<dim3(128, 24), 256>>>(seqp, LAT, 1, Wih0, LAT, bih0, gip, GATES, LAT);
    k_reset<<<1, 1>>>();
    k_gru_persist<<<NBLK, 192>>>(gip, (const ulonglong2*)Wb0p, bhh0, hAp, hBp, h1p, nn, 0);

    // Layer 1: gi = h1 @ Wih1^T + bih1    (M=8192, N=1536, K=512)
    k_gemm<<<dim3(128, 24), 256>>>(h1p, HID, 1, Wih1, HID, bih1, gip, GATES, HID);
    k_reset<<<1, 1>>>();
    k_gru_persist<<<NBLK, 192>>>(gip, (const ulonglong2*)Wb1p, bhh1, hAp, hBp, h2p, nn, 1);

    // Fold node_W into adjacency weights: WA = W1a @ node_W, WB = W1b @ node_W
    k_transpose<<<dim3(16, 16), dim3(32, 8)>>>(nW, nWTp);
    k_gemm<<<dim3(8, 8), 256>>>(aW1,       2 * HID, 0, nWTp, HID, nullptr, WAp, HID, HID);
    k_gemm<<<dim3(8, 8), 256>>>(aW1 + HID, 2 * HID, 0, nWTp, HID, nullptr, WBp, HID, HID);

    // A = rnn_out @ WA^T, B = rnn_out @ WB^T  (M=8192, N=512, K=512)
    k_gemm<<<dim3(128, 8), 256>>>(h2p, HID, 0, WAp, HID, nullptr, Amp, HID, HID);
    k_gemm<<<dim3(128, 8), 256>>>(h2p, HID, 0, WBp, HID, nullptr, Bmp, HID, HID);

    cudaMemsetAsync(out, 0, (size_t)out_size * sizeof(float), 0);
    k_pairs<<<dim3(126, 128), 256>>>(gum, nn, ab1, aW2, ab2, out);
}

// round 9
// speedup vs baseline: 1.5415x; 1.0703x over previous
#include <cuda_runtime.h>
#include <math.h>

// ---------------------------------------------------------------------------
// Constants
// ---------------------------------------------------------------------------
#define BATCHN 128
#define MN     64
#define LAT    256
#define HID    512
#define GATES  1536
#define NPAIRS 2016
#define EPSG   1e-10f

typedef unsigned long long ull;

// ---------------------------------------------------------------------------
// Static device scratch (no allocations anywhere)
// ---------------------------------------------------------------------------
__device__ float d_T1 [MN * LAT];                 // 64x256
__device__ float d_seq[BATCHN * MN * LAT];        // [b][t][256]
__device__ float d_gi [MN * BATCHN * GATES];      // [t][b][1536] (reused by both layers)
__device__ float d_h1 [BATCHN * MN * HID];        // layer0 outputs [b][t][512]
__device__ float d_h2 [BATCHN * MN * HID];        // layer1 outputs (masked) [b][t][512]
__device__ float d_Wb0[GATES * HID];              // Whh0 k-blocked [k4][1536][4]
__device__ float d_Wb1[GATES * HID];              // Whh1 k-blocked
__device__ float d_nWT[HID * HID];                // node_W transposed [k][d]
__device__ float d_WA [HID * HID];                // W1a @ node_W  (as [h][k])
__device__ float d_WB [HID * HID];                // W1b @ node_W
__device__ float d_Am [BATCHN * MN * HID];        // A[b,t,h]
__device__ float d_Bm [BATCHN * MN * HID];        // B[b,t,h]
__device__ int   d_pI [NPAIRS];
__device__ int   d_pJ [NPAIRS];

// ---------------------------------------------------------------------------
// f32x2 helpers (B300: 3-reg FFMA is half rate; f32x2 restores full rate)
// ---------------------------------------------------------------------------
__device__ __forceinline__ void fma2(ull &c, ull a, ull b) {
    asm("fma.rn.f32x2 %0, %1, %2, %0;" : "+l"(c) : "l"(a), "l"(b));
}
__device__ __forceinline__ float2 unpack2(ull v) {
    float2 r;
    asm("mov.b64 {%0,%1}, %2;" : "=f"(r.x), "=f"(r.y) : "l"(v));
    return r;
}

// ---------------------------------------------------------------------------
// Fused prep kernel (blocks partitioned by role) so the GRU kernel lands at
// stream launch index 3 (the launch ncu captures):
//   blocks [0,768)     : Whh0 -> k-blocked d_Wb0
//   blocks [768,1536)  : Whh1 -> k-blocked d_Wb1
//   block  1536        : pair index tables
//   blocks [1537,1601) : T1[t,o] = pe[t].Wpre[o,:256]+emb[t].Wpre[o,256:]+b_pre
// ---------------------------------------------------------------------------
__global__ void k_prep(const float4* __restrict__ W0, const float4* __restrict__ W1,
                       const float* __restrict__ pe, const float* __restrict__ emb,
                       const float* __restrict__ Wpre, const float* __restrict__ bpre) {
    __shared__ float sp[LAT], se[LAT];
    int bid = blockIdx.x, tid = threadIdx.x;
    if (bid < 768) {
        int idx = bid * 256 + tid;
        int row = idx >> 7, k4 = idx & 127;
        ((float4*)d_Wb0)[k4 * GATES + row] = W0[idx];
    } else if (bid < 1536) {
        int idx = (bid - 768) * 256 + tid;
        int row = idx >> 7, k4 = idx & 127;
        ((float4*)d_Wb1)[k4 * GATES + row] = W1[idx];
    } else if (bid == 1536) {
        int i = tid;
        if (i < MN - 1) {
            int start = i * (MN - 1) - i * (i - 1) / 2;
            for (int j = i + 1; j < MN; j++) {
                int p = start + (j - i - 1);
                d_pI[p] = i;
                d_pJ[p] = j;
            }
        }
    } else {
        int t = bid - 1537;              // 0..63
        int o = tid;                     // 0..255
        sp[o] = pe[t * LAT + o];
        se[o] = emb[t * LAT + o];
        __syncthreads();
        const float* w = Wpre + o * 2 * LAT;
        float acc = bpre[o];
#pragma unroll 4
        for (int k = 0; k < LAT; k++)
            acc = fmaf(sp[k], w[k], fmaf(se[k], w[LAT + k], acc));
        d_T1[t * LAT + o] = acc;
    }
}

// ---------------------------------------------------------------------------
// seq[b,t,o] = (z[b]·Wpre[o,:256] + T1[t,o]) * (t < n_nodes[b])
// ---------------------------------------------------------------------------
__global__ void k_seq(const float* __restrict__ z, const int* __restrict__ n_nodes,
                      const float* __restrict__ Wpre) {
    int b = blockIdx.x, o = threadIdx.x;
    __shared__ float sz[LAT];
    sz[o] = z[b * LAT + o];
    __syncthreads();
    const float* w = Wpre + o * 2 * LAT;
    float acc = 0.f;
#pragma unroll 4
    for (int k = 0; k < LAT; k++)
        acc = fmaf(sz[k], w[k], acc);
    int nb = n_nodes[b];
    for (int t = 0; t < MN; t++)
        d_seq[(b * MN + t) * LAT + o] = (t < nb) ? acc + d_T1[t * LAT + o] : 0.f;
}

// ---------------------------------------------------------------------------
// Generic NT GEMM: C[M][N] = A[M][K] * B[N][K]^T (+ bias[N])
//   remap=1: logical row m reads A at ((m%128)*64 + m/128)*ldA   (t-major gi)
//   BM=BN=64, BK=16, 256 threads, per-thread 4x4 via f32x2 (K-parity packed)
//   (single-buffer version: 92 regs, no spills)
// ---------------------------------------------------------------------------
__global__ __launch_bounds__(256, 2)
void k_gemm(const float* __restrict__ A, int ldA, int remap,
            const float* __restrict__ B, int ldB,
            const float* __restrict__ bias,
            float* __restrict__ C, int N, int K) {
    __shared__ float As[64 * 18];
    __shared__ float Bs[64 * 18];
    int tid = threadIdx.x;
    int ty = tid >> 4, tx = tid & 15;
    int m0 = blockIdx.x * 64, n0 = blockIdx.y * 64;
    int lrow = tid >> 2, kq = tid & 3;

    long aoff;
    {
        int arow = m0 + lrow;
        if (remap) {
            int bb = arow & 127, tt = arow >> 7;
            aoff = (long)(bb * MN + tt) * ldA;
        } else {
            aoff = (long)arow * ldA;
        }
    }
    long boff = (long)(n0 + lrow) * ldB;

    ull c2[4][4];
#pragma unroll
    for (int i = 0; i < 4; i++)
#pragma unroll
        for (int j = 0; j < 4; j++) c2[i][j] = 0ull;

    for (int k0 = 0; k0 < K; k0 += 16) {
        float4 av = *(const float4*)(A + aoff + k0 + kq * 4);
        float4 bv = *(const float4*)(B + boff + k0 + kq * 4);
        int sb = lrow * 18 + kq * 4;
        *(float2*)&As[sb]     = make_float2(av.x, av.y);
        *(float2*)&As[sb + 2] = make_float2(av.z, av.w);
        *(float2*)&Bs[sb]     = make_float2(bv.x, bv.y);
        *(float2*)&Bs[sb + 2] = make_float2(bv.z, bv.w);
        __syncthreads();
#pragma unroll
        for (int kk = 0; kk < 16; kk += 2) {
            ull a2[4], b2[4];
#pragma unroll
            for (int i = 0; i < 4; i++) a2[i] = *(const ull*)&As[(ty + 16 * i) * 18 + kk];
#pragma unroll
            for (int j = 0; j < 4; j++) b2[j] = *(const ull*)&Bs[(tx + 16 * j) * 18 + kk];
#pragma unroll
            for (int i = 0; i < 4; i++)
#pragma unroll
                for (int j = 0; j < 4; j++) fma2(c2[i][j], a2[i], b2[j]);
        }
        __syncthreads();
    }

#pragma unroll
    for (int i = 0; i < 4; i++) {
        int m = m0 + ty + 16 * i;
#pragma unroll
        for (int j = 0; j < 4; j++) {
            int n = n0 + tx + 16 * j;
            float2 v = unpack2(c2[i][j]);
            float val = v.x + v.y;
            if (bias) val += bias[n];
            C[(long)m * N + n] = val;
        }
    }
}

// ---------------------------------------------------------------------------
// Cluster-persistent GRU layer. Grid = 128 CTAs = 16 clusters of 8.
// Cluster = the 8 col-tile CTAs of one batch tile (8 batches). h state lives
// in double-buffered SMEM per CTA; each CTA pushes its 64-col slice of h(step)
// into all 8 cluster members' next buffer via DSMEM (mapa + st.shared::cluster),
// synchronized by barrier.cluster — no global h, no atomics, no spin.
// 384 threads = 12 warps (3/SMSP balanced); each row's 512-dot is split into
// two 256-k halves (kh) whose partials combine in SMEM.
// ---------------------------------------------------------------------------
__global__ void __cluster_dims__(8, 1, 1) __launch_bounds__(384, 1)
k_gru_cl(const float* __restrict__ gi,
         const ulonglong2* __restrict__ Wblk,    // k-blocked [k4][1536] (16B)
         const float* __restrict__ bhh,
         float* __restrict__ yout, const int* __restrict__ n_nodes,
         int maskout) {
    __shared__ __align__(16) float hbuf[2][8 * 512];   // [parity][batch][col]
    __shared__ float part[8][384];                      // partials / gh

    int tid = threadIdx.x;
    int r  = tid % 192;            // local row (3 gates x 64 cols)
    int kh = tid / 192;            // k half: 0 -> k[0,256), 1 -> k[256,512)
    int by = blockIdx.x & 7;       // cluster rank = col tile
    int bx = blockIdx.x >> 3;      // batch tile
    int b0 = bx * 8;

    int g = r / 64, j = r % 64;
    int row = g * 512 + by * 64 + j;
    const float bh = bhh[row];
    const ulonglong2* wp = Wblk + (long)(kh * 64) * GATES + row;

    // h(-1) = 0
    for (int idx = tid; idx < 1024; idx += 384)
        ((float4*)hbuf[0])[idx] = make_float4(0.f, 0.f, 0.f, 0.f);
    __syncthreads();

    for (int step = 0; step < MN; step++) {
        const float* hcur = hbuf[step & 1];
        const float* hk = hcur + kh * 256;

        // partial dot over this thread's k half, 8 batches
        ull acc[8];
#pragma unroll
        for (int b = 0; b < 8; b++) acc[b] = 0ull;
#pragma unroll 8
        for (int k4 = 0; k4 < 64; k4++) {
            ulonglong2 wv = wp[(long)k4 * GATES];      // coalesced across warp
#pragma unroll
            for (int b = 0; b < 8; b++) {
                ulonglong2 hv = *(const ulonglong2*)(hk + b * 512 + k4 * 4); // broadcast
                fma2(acc[b], wv.x, hv.x);
                fma2(acc[b], wv.y, hv.y);
            }
        }
#pragma unroll
        for (int b = 0; b < 8; b++) {
            float2 v = unpack2(acc[b]);
            part[b][tid] = v.x + v.y;
        }
        __syncthreads();

        // combine the two k-halves + bias -> gh in part[b][0..191]
        if (tid < 192) {
#pragma unroll
            for (int b = 0; b < 8; b++)
                part[b][tid] = part[b][tid] + part[b][tid + 192] + bh;
        }
        __syncthreads();

        // gate math + h update + DSMEM broadcast of new h slice
        float* hnx = hbuf[(step + 1) & 1];
        for (int idx = tid; idx < 512; idx += 384) {
            int b = idx >> 6, jj = idx & 63;
            int gb = b0 + b;
            int col = by * 64 + jj;
            long gbase = ((long)step * 128 + gb) * GATES;
            float ir  = gi[gbase + col];
            float iz  = gi[gbase + 512 + col];
            float inn = gi[gbase + 1024 + col];
            float hr = part[b][jj];
            float hz = part[b][64 + jj];
            float hn = part[b][128 + jj];
            float rr = 1.f / (1.f + expf(-(ir + hr)));
            float zg = 1.f / (1.f + expf(-(iz + hz)));
            float nn = tanhf(fmaf(rr, hn, inn));
            float hold = hcur[b * 512 + col];
            float hnew = (1.f - zg) * nn + zg * hold;
            float yv = hnew;
            if (maskout && step >= n_nodes[gb]) yv = 0.f;
            yout[((long)gb * MN + step) * HID + col] = yv;
            if (step < MN - 1) {
                unsigned la = (unsigned)__cvta_generic_to_shared(&hnx[b * 512 + col]);
#pragma unroll
                for (int t = 0; t < 8; t++) {
                    unsigned ra;
                    asm("mapa.shared::cluster.u32 %0, %1, %2;" : "=r"(ra) : "r"(la), "r"(t));
                    asm volatile("st.shared::cluster.f32 [%0], %1;" :: "r"(ra), "f"(hnew));
                }
            }
        }

        if (step < MN - 1) {
            asm volatile("barrier.cluster.arrive.aligned;" ::: "memory");
            asm volatile("barrier.cluster.wait.aligned;" ::: "memory");
        }
    }
}

// ---------------------------------------------------------------------------
// 512x512 transpose: dst[k][d] = src[d][k]
// ---------------------------------------------------------------------------
__global__ void k_transpose(const float* __restrict__ src, float* __restrict__ dst) {
    __shared__ float tile[32][33];
    int x = blockIdx.x * 32 + threadIdx.x;
    int y0 = blockIdx.y * 32;
    for (int r = threadIdx.y; r < 32; r += 8)
        tile[r][threadIdx.x] = src[(y0 + r) * HID + x];
    __syncthreads();
    int xo = blockIdx.y * 32 + threadIdx.x;
    int yo0 = blockIdx.x * 32;
    for (int r = threadIdx.y; r < 32; r += 8)
        dst[(yo0 + r) * HID + xo] = tile[threadIdx.x][r];
}

// ---------------------------------------------------------------------------
// Pair head: ld = sum_h relu(A[b,i,h]+B[b,j,h]+b1[h]) * (W2[0,h]-W2[1,h]) + b2d
// vals = 1 if ld + g0 - g1 >= 0. Writes only the 1s (out pre-zeroed).
// ---------------------------------------------------------------------------
__global__ __launch_bounds__(256)
void k_pairs(const float* __restrict__ gum, const int* __restrict__ n_nodes,
             const float* __restrict__ b1, const float* __restrict__ W2,
             const float* __restrict__ b2, float* __restrict__ out) {
    __shared__ float b1s[HID], w2s[HID];
    int b = blockIdx.y;
    int tid = threadIdx.x;
    for (int k = tid; k < HID; k += 256) {
        b1s[k] = b1[k];
        w2s[k] = W2[k] - W2[HID + k];
    }
    __syncthreads();
    int w = tid >> 5, lane = tid & 31;
    int nb = n_nodes[b];
    float b2d = b2[0] - b2[1];
#pragma unroll
    for (int q = 0; q < 2; q++) {
        int p = blockIdx.x * 16 + w * 2 + q;
        int i = d_pI[p], j = d_pJ[p];
        const float4* Ar = (const float4*)(d_Am + ((long)b * MN + i) * HID);
        const float4* Br = (const float4*)(d_Bm + ((long)b * MN + j) * HID);
        float acc = 0.f;
#pragma unroll
        for (int it = 0; it < 4; it++) {
            int k4 = it * 32 + lane;
            float4 a4 = Ar[k4];
            float4 b4 = Br[k4];
            int k = k4 * 4;
            float h0 = fmaxf(a4.x + b4.x + b1s[k],     0.f);
            float h1 = fmaxf(a4.y + b4.y + b1s[k + 1], 0.f);
            float h2 = fmaxf(a4.z + b4.z + b1s[k + 2], 0.f);
            float h3 = fmaxf(a4.w + b4.w + b1s[k + 3], 0.f);
            acc = fmaf(h0, w2s[k], acc);
            acc = fmaf(h1, w2s[k + 1], acc);
            acc = fmaf(h2, w2s[k + 2], acc);
            acc = fmaf(h3, w2s[k + 3], acc);
        }
#pragma unroll
        for (int off = 16; off; off >>= 1)
            acc += __shfl_xor_sync(0xffffffffu, acc, off);
        if (lane == 0 && j < nb) {
            const float* gu = gum + ((long)b * NPAIRS + p) * 2;
            float g0 = -logf(-logf(gu[0] + EPSG) + EPSG);
            float g1 = -logf(-logf(gu[1] + EPSG) + EPSG);
            float s = acc + b2d + g0 - g1;
            if (s >= 0.f) {
                out[(long)b * (MN * MN) + i * MN + j] = 1.f;
                out[(long)b * (MN * MN) + j * MN + i] = 1.f;
            }
        }
    }
}

// ---------------------------------------------------------------------------
// Host launch
// ---------------------------------------------------------------------------
extern "C" void kernel_launch(void* const* d_in, const int* in_sizes, int n_in,
                              void* d_out, int out_size) {
    // n_edges is an unused scalar; hedge on whether it appears as an input.
    int s = (n_in >= 21) ? 1 : 0;
    const float* z    = (const float*)d_in[0];
    const int*   nn   = (const int*)  d_in[1];
    const float* gum  = (const float*)d_in[2 + s];
    const float* emb  = (const float*)d_in[3 + s];
    const float* pe   = (const float*)d_in[4 + s];
    const float* Wpre = (const float*)d_in[5 + s];
    const float* bpre = (const float*)d_in[6 + s];
    const float* Wih0 = (const float*)d_in[7 + s];
    const float* Whh0 = (const float*)d_in[8 + s];
    const float* bih0 = (const float*)d_in[9 + s];
    const float* bhh0 = (const float*)d_in[10 + s];
    const float* Wih1 = (const float*)d_in[11 + s];
    const float* Whh1 = (const float*)d_in[12 + s];
    const float* bih1 = (const float*)d_in[13 + s];
    const float* bhh1 = (const float*)d_in[14 + s];
    const float* nW   = (const float*)d_in[15 + s];
    const float* aW1  = (const float*)d_in[16 + s];
    const float* ab1  = (const float*)d_in[17 + s];
    const float* aW2  = (const float*)d_in[18 + s];
    const float* ab2  = (const float*)d_in[19 + s];
    float* out = (float*)d_out;
    (void)in_sizes;

    float *seqp, *gip, *h1p, *h2p, *nWTp, *WAp, *WBp, *Amp, *Bmp, *Wb0p, *Wb1p;
    cudaGetSymbolAddress((void**)&seqp, d_seq);
    cudaGetSymbolAddress((void**)&gip,  d_gi);
    cudaGetSymbolAddress((void**)&h1p,  d_h1);
    cudaGetSymbolAddress((void**)&h2p,  d_h2);
    cudaGetSymbolAddress((void**)&nWTp, d_nWT);
    cudaGetSymbolAddress((void**)&WAp,  d_WA);
    cudaGetSymbolAddress((void**)&WBp,  d_WB);
    cudaGetSymbolAddress((void**)&Amp,  d_Am);
    cudaGetSymbolAddress((void**)&Bmp,  d_Bm);
    cudaGetSymbolAddress((void**)&Wb0p, d_Wb0);
    cudaGetSymbolAddress((void**)&Wb1p, d_Wb1);

    // launch 0: all weight/table prep fused
    k_prep<<<1601, 256>>>((const float4*)Whh0, (const float4*)Whh1,
                          pe, emb, Wpre, bpre);
    // launch 1
    k_seq<<<128, 256>>>(z, nn, Wpre);

    // launch 2: gi = seq @ Wih0^T + bih0   (M=8192, N=1536, K=256)
    k_gemm<<<dim3(128, 24), 256>>>(seqp, LAT, 1, Wih0, LAT, bih0, gip, GATES, LAT);
    // launch 3 (the one ncu captures): GRU layer 0
    k_gru_cl<<<128, 384>>>(gip, (const ulonglong2*)Wb0p, bhh0, h1p, nn, 0);

    // launch 4: gi = h1 @ Wih1^T + bih1    (M=8192, N=1536, K=512)
    k_gemm<<<dim3(128, 24), 256>>>(h1p, HID, 1, Wih1, HID, bih1, gip, GATES, HID);
    // launch 5: GRU layer 1
    k_gru_cl<<<128, 384>>>(gip, (const ulonglong2*)Wb1p, bhh1, h2p, nn, 1);

    // Fold node_W into adjacency weights: WA = W1a @ node_W, WB = W1b @ node_W
    k_transpose<<<dim3(16, 16), dim3(32, 8)>>>(nW, nWTp);
    k_gemm<<<dim3(8, 8), 256>>>(aW1,       2 * HID, 0, nWTp, HID, nullptr, WAp, HID, HID);
    k_gemm<<<dim3(8, 8), 256>>>(aW1 + HID, 2 * HID, 0, nWTp, HID, nullptr, WBp, HID, HID);

    // A = rnn_out @ WA^T, B = rnn_out @ WB^T  (M=8192, N=512, K=512)
    k_gemm<<<dim3(128, 8), 256>>>(h2p, HID, 0, WAp, HID, nullptr, Amp, HID, HID);
    k_gemm<<<dim3(128, 8), 256>>>(h2p, HID, 0, WBp, HID, nullptr, Bmp, HID, HID);

    cudaMemsetAsync(out, 0, (size_t)out_size * sizeof(float), 0);
    k_pairs<<<dim3(126, 128), 256>>>(gum, nn, ab1, aW2, ab2, out);
}